// round 2
// baseline (speedup 1.0000x reference)
#include <cuda_runtime.h>
#include <cuda_fp16.h>
#include <cstdint>

// LoroSparseLinear fused kernel.
// out = ((fp16(x) @ fp16(st24(w_in)*s_in).T) -> fp16 -> @ fp16(st24(w_out)*s_out).T + bias) / rank
//
// Shapes: x (8192, 4096) f32, w_in (64, 4096), w_out (4096, 64), bias (4096), out (8192, 4096) f32.
// Strategy: HBM-bound -> single pass over x. Per CTA: 32 rows.
//   GEMM1: K=4096 in chunks of 128, register-prefetch double buffer, mma.sync m16n8k16 (f16 in, f32 acc).
//   xp quantized to f16 in smem, A-frags for GEMM2 loaded once.
//   GEMM2: N=4096 in chunks of 128 (w_out chunk staged via smem, register-prefetched), epilogue streams out.

#define RANK   64
#define INF    4096
#define OUTF   4096
#define MTOT   8192
#define BM     32
#define BK     128
#define BN2    128
#define S1STR  136   // halves per row, stage-1 tiles (128 data + 8 pad; conflict-free for ldmatrix)
#define S2STR  72    // halves per row, stage-2 tiles (64 data + 8 pad)

__device__ __half g_sw_in[RANK * INF];    // (rank, in_f)  k-major
__device__ __half g_sw_out[OUTF * RANK];  // (out_f, rank) k-major

// ---------------------------------------------------------------------------
// Prep: 2:4 soft-threshold + scale + fp16 quantize for both weights.
// Groups of 4 are contiguous along the last dim for both tensors.
// ---------------------------------------------------------------------------
__global__ void prep_kernel(const float* __restrict__ win, const float* __restrict__ wout,
                            const float* __restrict__ s_in, const float* __restrict__ s_out) {
    int g = blockIdx.x * blockDim.x + threadIdx.x;
    const int NGI = RANK * INF / 4;
    const int NGO = OUTF * RANK / 4;
    if (g >= NGI + NGO) return;
    const float4* src;
    __half* dst;
    float scale;
    int gi;
    if (g < NGI) { src = (const float4*)win;  dst = g_sw_in;  scale = *s_in;  gi = g; }
    else         { src = (const float4*)wout; dst = g_sw_out; scale = *s_out; gi = g - NGI; }
    float4 w = src[gi];
    float m0 = fabsf(w.x), m1 = fabsf(w.y), m2 = fabsf(w.z), m3 = fabsf(w.w);
    float lo1 = fminf(m0, m1), hi1 = fmaxf(m0, m1);
    float lo2 = fminf(m2, m3), hi2 = fmaxf(m2, m3);
    // second-smallest of the 4 magnitudes
    float t = fminf(fmaxf(lo1, lo2), fminf(hi1, hi2));
    float o0 = copysignf(fmaxf(m0 - t, 0.f), w.x) * scale;
    float o1 = copysignf(fmaxf(m1 - t, 0.f), w.y) * scale;
    float o2 = copysignf(fmaxf(m2 - t, 0.f), w.z) * scale;
    float o3 = copysignf(fmaxf(m3 - t, 0.f), w.w) * scale;
    __half2* d2 = (__half2*)(dst + gi * 4);
    d2[0] = __floats2half2_rn(o0, o1);
    d2[1] = __floats2half2_rn(o2, o3);
}

// ---------------------------------------------------------------------------
// PTX helpers
// ---------------------------------------------------------------------------
__device__ __forceinline__ uint32_t sptr(const void* p) {
    return (uint32_t)__cvta_generic_to_shared(p);
}
__device__ __forceinline__ void ldm4(uint32_t& r0, uint32_t& r1, uint32_t& r2, uint32_t& r3,
                                     uint32_t addr) {
    asm volatile("ldmatrix.sync.aligned.m8n8.x4.shared.b16 {%0,%1,%2,%3},[%4];"
                 : "=r"(r0), "=r"(r1), "=r"(r2), "=r"(r3) : "r"(addr));
}
__device__ __forceinline__ void mma16816(float c[4], uint32_t a0, uint32_t a1, uint32_t a2,
                                         uint32_t a3, uint32_t b0, uint32_t b1) {
    asm volatile(
        "mma.sync.aligned.m16n8k16.row.col.f32.f16.f16.f32 "
        "{%0,%1,%2,%3},{%4,%5,%6,%7},{%8,%9},{%0,%1,%2,%3};"
        : "+f"(c[0]), "+f"(c[1]), "+f"(c[2]), "+f"(c[3])
        : "r"(a0), "r"(a1), "r"(a2), "r"(a3), "r"(b0), "r"(b1));
}

// ---------------------------------------------------------------------------
// Fused main kernel. 256 threads (8 warps), 2 CTAs/SM target.
// Warp tiling:
//   GEMM1: wm = (wid&1)*16 rows, wnr = (wid>>1)*16 rank-cols (2 n8 tiles)
//   GEMM2: wm rows, wn2 = (wid>>1)*32 out-cols (4 n8 tiles)
// ---------------------------------------------------------------------------
__global__ void __launch_bounds__(256, 2)
loro_kernel(const float* __restrict__ x, const float* __restrict__ bias,
            float* __restrict__ out) {
    // stage1: sA (BM x S1STR) + sB (RANK x S1STR) = 8704 + 17408 = 26112 B
    // stage2 (overlaps stage1): sXp (BM x S2STR) = 4608 B, sW (BN2 x S2STR) = 18432 B
    __shared__ __align__(16) char smem_raw[(BM * S1STR + RANK * S1STR) * 2];
    __half* sA  = (__half*)smem_raw;
    __half* sB  = (__half*)(smem_raw + BM * S1STR * 2);
    __half* sXp = (__half*)smem_raw;
    __half* sW  = (__half*)(smem_raw + BM * S2STR * 2);

    const int tid  = threadIdx.x;
    const int lane = tid & 31;
    const int wid  = tid >> 5;
    const int m0   = blockIdx.x * BM;
    const int wm   = (wid & 1) << 4;
    const int wnr  = (wid >> 1) << 4;
    const int wn2  = (wid >> 1) << 5;

    float c1[2][4] = {};

    const float4* x4 = (const float4*)x;
    const uint4*  w4 = (const uint4*)g_sw_in;

    float4 xr[4];
    uint4  wr[4];

    // prologue: load K-chunk 0
#pragma unroll
    for (int i = 0; i < 4; i++) {
        int f = tid + i * 256;
        xr[i] = x4[(size_t)(m0 + (f >> 5)) * 1024 + (f & 31)];
    }
#pragma unroll
    for (int i = 0; i < 4; i++) {
        int f = tid + i * 256;
        wr[i] = w4[(f >> 4) * 512 + (f & 15)];
    }

    // =================== GEMM1: xp = fp16(x) @ sw_in^T ===================
    for (int kb = 0; kb < INF / BK; kb++) {
#pragma unroll
        for (int i = 0; i < 4; i++) {
            int f = tid + i * 256;
            int row = f >> 5, c4 = f & 31;
            __half2* d = (__half2*)(sA + row * S1STR + c4 * 4);
            d[0] = __floats2half2_rn(xr[i].x, xr[i].y);
            d[1] = __floats2half2_rn(xr[i].z, xr[i].w);
        }
#pragma unroll
        for (int i = 0; i < 4; i++) {
            int f = tid + i * 256;
            *(uint4*)(sB + (f >> 4) * S1STR + (f & 15) * 8) = wr[i];
        }
        __syncthreads();

        if (kb + 1 < INF / BK) {
            int k0f = (kb + 1) * 32;   // float4 offset within a row
            int k0h = (kb + 1) * 16;   // uint4 offset within a w_in row
#pragma unroll
            for (int i = 0; i < 4; i++) {
                int f = tid + i * 256;
                xr[i] = x4[(size_t)(m0 + (f >> 5)) * 1024 + k0f + (f & 31)];
            }
#pragma unroll
            for (int i = 0; i < 4; i++) {
                int f = tid + i * 256;
                wr[i] = w4[(f >> 4) * 512 + k0h + (f & 15)];
            }
        }

#pragma unroll
        for (int ks = 0; ks < BK / 16; ks++) {
            int k = ks * 16;
            uint32_t a0, a1, a2, a3, b0, b1, b2, b3;
            {
                int r  = wm + (lane & 7) + ((lane >> 3) & 1) * 8;
                int cc = k + (lane >> 4) * 8;
                ldm4(a0, a1, a2, a3, sptr(sA + r * S1STR + cc));
            }
            {
                int bn = wnr + (lane & 7) + (lane >> 4) * 8;
                int bc = k + ((lane >> 3) & 1) * 8;
                ldm4(b0, b1, b2, b3, sptr(sB + bn * S1STR + bc));
            }
            mma16816(c1[0], a0, a1, a2, a3, b0, b1);
            mma16816(c1[1], a0, a1, a2, a3, b2, b3);
        }
        __syncthreads();
    }

    // quantize xp -> fp16 into sXp (this is the fp16 cast fp8_mm applies to xp)
    {
        int row  = wm + (lane >> 2);
        int colb = wnr + (lane & 3) * 2;
#pragma unroll
        for (int j = 0; j < 2; j++) {
            *(__half2*)(sXp + row * S2STR + colb + j * 8) =
                __floats2half2_rn(c1[j][0], c1[j][1]);
            *(__half2*)(sXp + (row + 8) * S2STR + colb + j * 8) =
                __floats2half2_rn(c1[j][2], c1[j][3]);
        }
    }
    __syncthreads();

    // GEMM2 A-frags: xp rows wm..wm+15, K = 64 (4 k-steps), loaded once.
    uint32_t a2r[4][4];
#pragma unroll
    for (int ks = 0; ks < 4; ks++) {
        int r  = wm + (lane & 7) + ((lane >> 3) & 1) * 8;
        int cc = ks * 16 + (lane >> 4) * 8;
        ldm4(a2r[ks][0], a2r[ks][1], a2r[ks][2], a2r[ks][3], sptr(sXp + r * S2STR + cc));
    }

    // =================== GEMM2: out = fp16(xp) @ sw_out^T ===================
    const uint4* wo4 = (const uint4*)g_sw_out;
    uint4 wreg[4];
#pragma unroll
    for (int i = 0; i < 4; i++) {
        int f = tid + i * 256;
        wreg[i] = wo4[(size_t)(f >> 3) * 8 + (f & 7)];
    }

    const float scaling = 1.0f / RANK;
    for (int nc = 0; nc < OUTF / BN2; nc++) {
#pragma unroll
        for (int i = 0; i < 4; i++) {
            int f = tid + i * 256;
            *(uint4*)(sW + (f >> 3) * S2STR + (f & 7) * 8) = wreg[i];
        }
        __syncthreads();

        if (nc + 1 < OUTF / BN2) {
            int n0n = (nc + 1) * BN2;
#pragma unroll
            for (int i = 0; i < 4; i++) {
                int f = tid + i * 256;
                wreg[i] = wo4[(size_t)(n0n + (f >> 3)) * 8 + (f & 7)];
            }
        }

        float c2[4][4] = {};
#pragma unroll
        for (int ks = 0; ks < 4; ks++) {
            int k = ks * 16;
            int bc = k + ((lane >> 3) & 1) * 8;
            uint32_t b0, b1, b2, b3;
            {
                int bn = wn2 + (lane & 7) + (lane >> 4) * 8;
                ldm4(b0, b1, b2, b3, sptr(sW + bn * S2STR + bc));
            }
            mma16816(c2[0], a2r[ks][0], a2r[ks][1], a2r[ks][2], a2r[ks][3], b0, b1);
            mma16816(c2[1], a2r[ks][0], a2r[ks][1], a2r[ks][2], a2r[ks][3], b2, b3);
            {
                int bn = wn2 + 16 + (lane & 7) + (lane >> 4) * 8;
                ldm4(b0, b1, b2, b3, sptr(sW + bn * S2STR + bc));
            }
            mma16816(c2[2], a2r[ks][0], a2r[ks][1], a2r[ks][2], a2r[ks][3], b0, b1);
            mma16816(c2[3], a2r[ks][0], a2r[ks][1], a2r[ks][2], a2r[ks][3], b2, b3);
        }
        __syncthreads();

        // epilogue: (acc + bias) * (1/rank) -> gmem
        int n0   = nc * BN2;
        int rowg = m0 + wm + (lane >> 2);
#pragma unroll
        for (int j = 0; j < 4; j++) {
            int col = n0 + wn2 + j * 8 + (lane & 3) * 2;
            float2 bv = *(const float2*)(bias + col);
            float2 o;
            o.x = (c2[j][0] + bv.x) * scaling;
            o.y = (c2[j][1] + bv.y) * scaling;
            *(float2*)(out + (size_t)rowg * OUTF + col) = o;
            o.x = (c2[j][2] + bv.x) * scaling;
            o.y = (c2[j][3] + bv.y) * scaling;
            *(float2*)(out + (size_t)(rowg + 8) * OUTF + col) = o;
        }
    }
}

// ---------------------------------------------------------------------------
extern "C" void kernel_launch(void* const* d_in, const int* in_sizes, int n_in,
                              void* d_out, int out_size) {
    const float* x     = (const float*)d_in[0];
    const float* win   = (const float*)d_in[1];
    const float* wout  = (const float*)d_in[2];
    const float* bias  = (const float*)d_in[3];
    const float* s_in  = (const float*)d_in[4];
    const float* s_out = (const float*)d_in[5];
    float* out = (float*)d_out;

    int ng = (RANK * INF + OUTF * RANK) / 4;
    prep_kernel<<<(ng + 255) / 256, 256>>>(win, wout, s_in, s_out);
    loro_kernel<<<MTOT / BM, 256>>>(x, bias, out);
}